// round 16
// baseline (speedup 1.0000x reference)
#include <cuda_runtime.h>

#define NN 100000
#define EE 3200000
#define FF 32
#define NG 8
#define BN_EPS 1e-5f
#define CHUNKS ((NN + 1023) / 1024)   // 98

// ---------------- scratch ----------------
__device__ float g_dinv[NN];
__device__ int   g_cnt[NN];
__device__ int   g_ptr[NN];          // after scan: exclusive prefix; after scatter: segment end
__device__ int   g_agg[CHUNKS];
__device__ volatile int g_flag[CHUNKS];
__device__ int2  g_edge[EE];         // packed (src, w-as-int), sorted by dst
__device__ float g_ht[NN * FF];      // dinv-prescaled transformed features
__device__ float g_y[NN * FF];
__device__ float g_stats[5 * 128];   // per-stage BN stats
__device__ float g_pool[NG * FF];
__device__ float g_pcnt[NG];

// ---------------- kernels ----------------

__global__ void k_zero() {
    int i = blockIdx.x * blockDim.x + threadIdx.x;
    if (i < NN)       g_cnt[i]  = 0;
    if (i < CHUNKS)   g_flag[i] = 0;
    if (i < 5 * 128)  g_stats[i] = 0.f;
    if (i < NG * FF)  g_pool[i]  = 0.f;
    if (i < NG)       g_pcnt[i]  = 0.f;
}

// 4 edges/thread: vector load of cols, 4 independent atomics (EE % 4 == 0)
__global__ void k_degcnt(const int* __restrict__ ei) {
    int e4 = blockIdx.x * blockDim.x + threadIdx.x;
    if (e4 < EE / 4) {
        int4 c4 = ((const int4*)(ei + EE))[e4];
        atomicAdd(&g_cnt[c4.x], 1);
        atomicAdd(&g_cnt[c4.y], 1);
        atomicAdd(&g_cnt[c4.z], 1);
        atomicAdd(&g_cnt[c4.w], 1);
    }
}

// single-pass scan with decoupled lookback (98 blocks, all resident)
__global__ void k_scanlb() {
    __shared__ int wsum[32];
    __shared__ int carry;
    int t = threadIdx.x, b = blockIdx.x;
    int i = b * 1024 + t;
    int v = (i < NN) ? g_cnt[i] : 0;
    int xx = v;
#pragma unroll
    for (int off = 1; off < 32; off <<= 1) {
        int u = __shfl_up_sync(0xffffffffu, xx, off);
        if ((t & 31) >= off) xx += u;
    }
    if ((t & 31) == 31) wsum[t >> 5] = xx;
    __syncthreads();
    if (t < 32) {
        int y = wsum[t];
#pragma unroll
        for (int off = 1; off < 32; off <<= 1) {
            int u = __shfl_up_sync(0xffffffffu, y, off);
            if (t >= off) y += u;
        }
        wsum[t] = y;
    }
    __syncthreads();
    int incl = xx + ((t >= 32) ? wsum[(t >> 5) - 1] : 0);
    if (t == 1023) {
        g_agg[b] = incl;
        __threadfence();
        g_flag[b] = 1;
    }
    if (t == 0) carry = 0;
    __syncthreads();
    if (t < b) {
        while (g_flag[t] == 0) { }
        atomicAdd(&carry, g_agg[t]);
    }
    __syncthreads();
    if (i < NN) g_ptr[i] = incl - v + carry;   // exclusive global prefix
}

// fill CSC: 4 edges/thread, 4 independent atomic->store chains.
// Afterwards g_ptr[c] == segment end of c.
__global__ void k_scatter(const int* __restrict__ ei, const float* __restrict__ w) {
    int e4 = blockIdx.x * blockDim.x + threadIdx.x;
    if (e4 < EE / 4) {
        int4   r4 = ((const int4*)ei)[e4];
        int4   c4 = ((const int4*)(ei + EE))[e4];
        float4 w4 = ((const float4*)w)[e4];
        int p0 = atomicAdd(&g_ptr[c4.x], 1);
        int p1 = atomicAdd(&g_ptr[c4.y], 1);
        int p2 = atomicAdd(&g_ptr[c4.z], 1);
        int p3 = atomicAdd(&g_ptr[c4.w], 1);
        g_edge[p0] = make_int2(r4.x, __float_as_int(w4.x));
        g_edge[p1] = make_int2(r4.y, __float_as_int(w4.y));
        g_edge[p2] = make_int2(r4.z, __float_as_int(w4.z));
        g_edge[p3] = make_int2(r4.w, __float_as_int(w4.w));
    }
}

__global__ void k_dinv2() {
    int gw = (blockIdx.x * blockDim.x + threadIdx.x) >> 5;
    int lane = threadIdx.x & 31;
    if (gw >= NN) return;
    int s0 = (gw == 0) ? 0 : g_ptr[gw - 1];
    int s1 = g_ptr[gw];
    float s = 0.f;
    for (int i = s0 + lane; i < s1; i += 32) s += __int_as_float(g_edge[i].y);
#pragma unroll
    for (int off = 16; off; off >>= 1) s += __shfl_xor_sync(0xffffffffu, s, off);
    if (lane == 0) {
        float d = 1.0f + s;
        g_dinv[gw] = (d > 0.f) ? rsqrtf(d) : 0.f;
    }
}

// BN stats of raw input x (13 channels) -> stats slot 0
__global__ void k_xstats(const float* __restrict__ x) {
    __shared__ float ss[13], sq[13];
    int t = threadIdx.x;
    if (t < 13) { ss[t] = 0.f; sq[t] = 0.f; }
    __syncthreads();
    int row = blockIdx.x * blockDim.x + t;
    float v[13];
#pragma unroll
    for (int ch = 0; ch < 13; ch++) v[ch] = (row < NN) ? x[row * 13 + ch] : 0.f;
#pragma unroll
    for (int ch = 0; ch < 13; ch++) {
        float s = v[ch], q = v[ch] * v[ch];
#pragma unroll
        for (int off = 16; off; off >>= 1) {
            s += __shfl_xor_sync(0xffffffffu, s, off);
            q += __shfl_xor_sync(0xffffffffu, q, off);
        }
        if ((t & 31) == 0) { atomicAdd(&ss[ch], s); atomicAdd(&sq[ch], q); }
    }
    __syncthreads();
    if (t < 13) { atomicAdd(&g_stats[t], ss[t]); atomicAdd(&g_stats[64 + t], sq[t]); }
}

// first-layer matmul (din=13): ht = dinv * (bn(x) @ W)
__global__ void k_matmul13(const float* __restrict__ in, const float* __restrict__ W,
                           const float* __restrict__ gma, const float* __restrict__ bta) {
    __shared__ float Wsh[13 * 32];
    __shared__ float ssh[13], shsh[13];
    int t = threadIdx.x;
    for (int i = t; i < 13 * 32; i += 256) Wsh[i] = W[i];
    if (t < 13) {
        float inv_n = 1.0f / (float)NN;
        float mu  = g_stats[t] * inv_n;
        float var = g_stats[64 + t] * inv_n - mu * mu;
        float sc  = gma[t] * rsqrtf(var + BN_EPS);
        ssh[t]  = sc;
        shsh[t] = bta[t] - mu * sc;
    }
    __syncthreads();
    int warp = t >> 5, j = t & 31;
    int node = blockIdx.x * 8 + warp;
    if (node >= NN) return;
    float a = (j < 13) ? (ssh[j] * in[node * 13 + j] + shsh[j]) : 0.f;
    float acc = 0.f;
#pragma unroll
    for (int k = 0; k < 13; k++) {
        float ak = __shfl_sync(0xffffffffu, a, k);
        acc += ak * Wsh[k * 32 + j];
    }
    g_ht[node * 32 + j] = acc * g_dinv[node];
}

// din=32 matmul: 4 nodes/warp, float4 lanes
__global__ void k_matmul32(const float* __restrict__ W, const float* __restrict__ st,
                           const float* __restrict__ gma, const float* __restrict__ bta) {
    __shared__ float4 Wsh4[32 * 8];
    __shared__ float ssh[32], shsh[32];
    int t = threadIdx.x;   // 256
    for (int i = t; i < 32 * 8; i += 256) Wsh4[i] = ((const float4*)W)[i];
    if (t < 32) {
        float inv_n = 1.0f / (float)NN;
        float mu  = st[t] * inv_n;
        float var = st[64 + t] * inv_n - mu * mu;
        float sc  = gma[t] * rsqrtf(var + BN_EPS);
        ssh[t]  = sc;
        shsh[t] = bta[t] - mu * sc;
    }
    __syncthreads();
    int warp = t >> 5, lane = t & 31;
    int l = lane & 7;
    int node = (blockIdx.x * 8 + warp) * 4 + (lane >> 3);
    float4 a4 = ((const float4*)g_y)[node * 8 + l];
    a4.x = ssh[l * 4 + 0] * a4.x + shsh[l * 4 + 0];
    a4.y = ssh[l * 4 + 1] * a4.y + shsh[l * 4 + 1];
    a4.z = ssh[l * 4 + 2] * a4.z + shsh[l * 4 + 2];
    a4.w = ssh[l * 4 + 3] * a4.w + shsh[l * 4 + 3];
    float4 acc = make_float4(0.f, 0.f, 0.f, 0.f);
    int grpbase = lane & 24;
#pragma unroll
    for (int k = 0; k < 32; k++) {
        float comp = ((k & 3) == 0) ? a4.x : ((k & 3) == 1) ? a4.y : ((k & 3) == 2) ? a4.z : a4.w;
        float ak = __shfl_sync(0xffffffffu, comp, grpbase + (k >> 2));
        float4 wv = Wsh4[k * 8 + l];
        acc.x += ak * wv.x; acc.y += ak * wv.y; acc.z += ak * wv.z; acc.w += ak * wv.w;
    }
    float dvn = g_dinv[node];
    acc.x *= dvn; acc.y *= dvn; acc.z *= dvn; acc.w *= dvn;
    ((float4*)g_ht)[node * 8 + l] = acc;
}

// SpMM: batched full chunks (MLP=8) + masked tail. Segment = [ptr[c-1], ptr[c]).
// do_pool != 0 (last layer): pool into per-graph buckets instead of storing y.
__global__ void k_spmm(const float* __restrict__ b, float* __restrict__ st,
                       const int* __restrict__ batch, int do_pool) {
    __shared__ float bsh[32], bsum[32], bsq[32];
    __shared__ float psh[NG * 32];
    __shared__ float pcs[NG];
    int t = threadIdx.x;
    if (t < 32) { bsh[t] = b[t]; bsum[t] = 0.f; bsq[t] = 0.f; }
    if (do_pool) {
        if (t < NG * 32) psh[t] = 0.f;
        if (t < NG)      pcs[t] = 0.f;
    }
    __syncthreads();
    int warp = t >> 5, lane = t & 31;
    int g = lane >> 3, l = lane & 7;
    int c = blockIdx.x * 32 + warp;       // NN = 3125*32
    const float4* ht4 = (const float4*)g_ht;
    int s0 = (c == 0) ? 0 : g_ptr[c - 1];
    int s1 = g_ptr[c];
    float dv = g_dinv[c];
    float4 h0 = ht4[c * 8 + l];
    float4 acc = make_float4(0.f, 0.f, 0.f, 0.f);

    int nfull = (s1 - s0) & ~31;
    int full_end = s0 + nfull;
    for (int base = s0; base < full_end; base += 32) {
        int2 ew = g_edge[base + lane];
        int   ssrc[8];
        float wwt[8];
#pragma unroll
        for (int q = 0; q < 8; q++) {
            ssrc[q] = __shfl_sync(0xffffffffu, ew.x, q * 4 + g);
            wwt[q]  = __int_as_float(__shfl_sync(0xffffffffu, ew.y, q * 4 + g));
        }
        float4 hv[8];
#pragma unroll
        for (int q = 0; q < 8; q++) hv[q] = ht4[ssrc[q] * 8 + l];
#pragma unroll
        for (int q = 0; q < 8; q++) {
            acc.x += wwt[q] * hv[q].x; acc.y += wwt[q] * hv[q].y;
            acc.z += wwt[q] * hv[q].z; acc.w += wwt[q] * hv[q].w;
        }
    }
    if (full_end < s1) {
        int idx = full_end + lane;
        int2 ew = (idx < s1) ? g_edge[idx] : make_int2(0, 0);
        int m = s1 - full_end;
        int iters = (m + 3) >> 2;
        for (int q = 0; q < iters; q++) {
            int srcl = q * 4 + g;
            int   ss = __shfl_sync(0xffffffffu, ew.x, srcl);
            float ww = __int_as_float(__shfl_sync(0xffffffffu, ew.y, srcl));
            float4 hv = ht4[ss * 8 + l];
            acc.x += ww * hv.x; acc.y += ww * hv.y; acc.z += ww * hv.z; acc.w += ww * hv.w;
        }
    }
#pragma unroll
    for (int off = 8; off <= 16; off <<= 1) {
        acc.x += __shfl_xor_sync(0xffffffffu, acc.x, off);
        acc.y += __shfl_xor_sync(0xffffffffu, acc.y, off);
        acc.z += __shfl_xor_sync(0xffffffffu, acc.z, off);
        acc.w += __shfl_xor_sync(0xffffffffu, acc.w, off);
    }
    float4 r4;
    r4.x = fmaxf(dv * (acc.x + h0.x) + bsh[l * 4 + 0], 0.f);
    r4.y = fmaxf(dv * (acc.y + h0.y) + bsh[l * 4 + 1], 0.f);
    r4.z = fmaxf(dv * (acc.z + h0.z) + bsh[l * 4 + 2], 0.f);
    r4.w = fmaxf(dv * (acc.w + h0.w) + bsh[l * 4 + 3], 0.f);
    if (g == 0) {
        atomicAdd(&bsum[l * 4 + 0], r4.x); atomicAdd(&bsq[l * 4 + 0], r4.x * r4.x);
        atomicAdd(&bsum[l * 4 + 1], r4.y); atomicAdd(&bsq[l * 4 + 1], r4.y * r4.y);
        atomicAdd(&bsum[l * 4 + 2], r4.z); atomicAdd(&bsq[l * 4 + 2], r4.z * r4.z);
        atomicAdd(&bsum[l * 4 + 3], r4.w); atomicAdd(&bsq[l * 4 + 3], r4.w * r4.w);
        if (do_pool) {
            int bg = batch[c];
            atomicAdd(&psh[bg * 32 + l * 4 + 0], r4.x);
            atomicAdd(&psh[bg * 32 + l * 4 + 1], r4.y);
            atomicAdd(&psh[bg * 32 + l * 4 + 2], r4.z);
            atomicAdd(&psh[bg * 32 + l * 4 + 3], r4.w);
            if (l == 0) atomicAdd(&pcs[bg], 1.f);
        } else {
            ((float4*)g_y)[c * 8 + l] = r4;
        }
    }
    __syncthreads();
    if (t < 32) { atomicAdd(&st[t], bsum[t]); atomicAdd(&st[64 + t], bsq[t]); }
    if (do_pool) {
        if (t < NG * 32) atomicAdd(&g_pool[t], psh[t]);
        if (t < NG)      atomicAdd(&g_pcnt[t], pcs[t]);
    }
}

// final: BN4 fold (stats slot 4) applied to per-graph means
__global__ void k_final(float* __restrict__ out,
                        const float* __restrict__ gma, const float* __restrict__ bta) {
    int t = threadIdx.x;        // 256
    int j = t & 31, g = t >> 5;
    const float* st = g_stats + 4 * 128;
    float inv_n = 1.0f / (float)NN;
    float mu  = st[j] * inv_n;
    float var = st[64 + j] * inv_n - mu * mu;
    float sc  = gma[j] * rsqrtf(var + BN_EPS);
    float sh  = bta[j] - mu * sc;
    float c = g_pcnt[g];
    if (c < 1.f) c = 1.f;
    out[t] = sc * (g_pool[t] / c) + sh;
}

// ---------------- launch ----------------
extern "C" void kernel_launch(void* const* d_in, const int* in_sizes, int n_in,
                              void* d_out, int out_size) {
    const float* x     = (const float*)d_in[0];
    const int*   ei    = (const int*)d_in[1];     // int32 (jax x64 disabled)
    const float* w     = (const float*)d_in[2];
    const int*   batch = (const int*)d_in[3];
    const float* W[4] = {(const float*)d_in[4], (const float*)d_in[6],
                         (const float*)d_in[8], (const float*)d_in[10]};
    const float* B[4] = {(const float*)d_in[5], (const float*)d_in[7],
                         (const float*)d_in[9], (const float*)d_in[11]};
    const float* G[5]; const float* BE[5];
    for (int i = 0; i < 5; i++) {
        G[i]  = (const float*)d_in[12 + 2 * i];
        BE[i] = (const float*)d_in[13 + 2 * i];
    }
    float* out = (float*)d_out;

    float* stats_base = nullptr;
    cudaGetSymbolAddress((void**)&stats_base, g_stats);

    k_zero<<<(NN + 255) / 256, 256>>>();                 // #0
    k_degcnt<<<(EE / 4 + 255) / 256, 256>>>(ei);         // #1
    k_scanlb<<<CHUNKS, 1024>>>();                        // #2
    k_scatter<<<(EE / 4 + 255) / 256, 256>>>(ei, w);     // #3  <- profiled slot
    k_dinv2<<<(NN + 7) / 8, 256>>>();                    // #4
    k_xstats<<<(NN + 255) / 256, 256>>>(x);              // #5

    for (int l = 0; l < 4; l++) {
        if (l == 0) k_matmul13<<<(NN + 7) / 8, 256>>>(x, W[0], G[0], BE[0]);
        else        k_matmul32<<<NN / 32, 256>>>(W[l], stats_base + 128 * l, G[l], BE[l]);
        k_spmm<<<NN / 32, 1024>>>(B[l], stats_base + 128 * (l + 1), batch, (l == 3) ? 1 : 0);
    }

    k_final<<<1, 256>>>(out, G[4], BE[4]);
}

// round 17
// speedup vs baseline: 1.0135x; 1.0135x over previous
#include <cuda_runtime.h>

#define NN 100000
#define EE 3200000
#define FF 32
#define NG 8
#define BN_EPS 1e-5f
#define CHUNKS ((NN + 1023) / 1024)   // 98

// ---------------- scratch ----------------
__device__ float g_dinv[NN];
__device__ int   g_cnt[NN];
__device__ int   g_ptr[NN + 1];      // exclusive prefix (immutable after scan); g_ptr[NN]=EE
__device__ int   g_rank[EE];         // per-edge rank within destination (from histogram)
__device__ int   g_agg[CHUNKS];
__device__ volatile int g_flag[CHUNKS];
__device__ int2  g_edge[EE];         // packed (src, w-as-int), sorted by dst
__device__ float g_ht[NN * FF];      // dinv-prescaled transformed features
__device__ float g_y[NN * FF];
__device__ float g_stats[5 * 128];   // per-stage BN stats
__device__ float g_pool[NG * FF];
__device__ float g_pcnt[NG];

// ---------------- kernels ----------------

__global__ void k_zero() {
    int i = blockIdx.x * blockDim.x + threadIdx.x;
    if (i < NN)       g_cnt[i]  = 0;
    if (i < CHUNKS)   g_flag[i] = 0;
    if (i < 5 * 128)  g_stats[i] = 0.f;
    if (i < NG * FF)  g_pool[i]  = 0.f;
    if (i < NG)       g_pcnt[i]  = 0.f;
}

// histogram; SAVE the returned rank per edge (4 edges/thread, EE % 4 == 0)
__global__ void k_degcnt(const int* __restrict__ ei) {
    int e4 = blockIdx.x * blockDim.x + threadIdx.x;
    if (e4 < EE / 4) {
        int4 c4 = ((const int4*)(ei + EE))[e4];
        int4 rk;
        rk.x = atomicAdd(&g_cnt[c4.x], 1);
        rk.y = atomicAdd(&g_cnt[c4.y], 1);
        rk.z = atomicAdd(&g_cnt[c4.z], 1);
        rk.w = atomicAdd(&g_cnt[c4.w], 1);
        ((int4*)g_rank)[e4] = rk;
    }
}

// single-pass scan with decoupled lookback (98 blocks, all resident)
__global__ void k_scanlb() {
    __shared__ int wsum[32];
    __shared__ int carry;
    int t = threadIdx.x, b = blockIdx.x;
    int i = b * 1024 + t;
    int v = (i < NN) ? g_cnt[i] : 0;
    int xx = v;
#pragma unroll
    for (int off = 1; off < 32; off <<= 1) {
        int u = __shfl_up_sync(0xffffffffu, xx, off);
        if ((t & 31) >= off) xx += u;
    }
    if ((t & 31) == 31) wsum[t >> 5] = xx;
    __syncthreads();
    if (t < 32) {
        int y = wsum[t];
#pragma unroll
        for (int off = 1; off < 32; off <<= 1) {
            int u = __shfl_up_sync(0xffffffffu, y, off);
            if (t >= off) y += u;
        }
        wsum[t] = y;
    }
    __syncthreads();
    int incl = xx + ((t >= 32) ? wsum[(t >> 5) - 1] : 0);
    if (t == 1023) {
        g_agg[b] = incl;
        __threadfence();
        g_flag[b] = 1;
    }
    if (t == 0) carry = 0;
    __syncthreads();
    if (t < b) {
        while (g_flag[t] == 0) { }
        atomicAdd(&carry, g_agg[t]);
    }
    __syncthreads();
    if (i <= NN) g_ptr[i] = incl - v + carry;   // exclusive prefix; g_ptr[NN] = EE
}

// fill CSC WITHOUT atomics: pos = prefix[c] + rank[e] (4 edges/thread)
__global__ void k_scatter(const int* __restrict__ ei, const float* __restrict__ w) {
    int e4 = blockIdx.x * blockDim.x + threadIdx.x;
    if (e4 < EE / 4) {
        int4   r4 = ((const int4*)ei)[e4];
        int4   c4 = ((const int4*)(ei + EE))[e4];
        float4 w4 = ((const float4*)w)[e4];
        int4   rk = ((const int4*)g_rank)[e4];
        int p0 = g_ptr[c4.x] + rk.x;    // plain random loads: pipelinable, no RMW
        int p1 = g_ptr[c4.y] + rk.y;
        int p2 = g_ptr[c4.z] + rk.z;
        int p3 = g_ptr[c4.w] + rk.w;
        g_edge[p0] = make_int2(r4.x, __float_as_int(w4.x));
        g_edge[p1] = make_int2(r4.y, __float_as_int(w4.y));
        g_edge[p2] = make_int2(r4.z, __float_as_int(w4.z));
        g_edge[p3] = make_int2(r4.w, __float_as_int(w4.w));
    }
}

__global__ void k_dinv2() {
    int gw = (blockIdx.x * blockDim.x + threadIdx.x) >> 5;
    int lane = threadIdx.x & 31;
    if (gw >= NN) return;
    int s0 = g_ptr[gw], s1 = g_ptr[gw + 1];
    float s = 0.f;
    for (int i = s0 + lane; i < s1; i += 32) s += __int_as_float(g_edge[i].y);
#pragma unroll
    for (int off = 16; off; off >>= 1) s += __shfl_xor_sync(0xffffffffu, s, off);
    if (lane == 0) {
        float d = 1.0f + s;
        g_dinv[gw] = (d > 0.f) ? rsqrtf(d) : 0.f;
    }
}

// BN stats of raw input x (13 channels) -> stats slot 0
__global__ void k_xstats(const float* __restrict__ x) {
    __shared__ float ss[13], sq[13];
    int t = threadIdx.x;
    if (t < 13) { ss[t] = 0.f; sq[t] = 0.f; }
    __syncthreads();
    int row = blockIdx.x * blockDim.x + t;
    float v[13];
#pragma unroll
    for (int ch = 0; ch < 13; ch++) v[ch] = (row < NN) ? x[row * 13 + ch] : 0.f;
#pragma unroll
    for (int ch = 0; ch < 13; ch++) {
        float s = v[ch], q = v[ch] * v[ch];
#pragma unroll
        for (int off = 16; off; off >>= 1) {
            s += __shfl_xor_sync(0xffffffffu, s, off);
            q += __shfl_xor_sync(0xffffffffu, q, off);
        }
        if ((t & 31) == 0) { atomicAdd(&ss[ch], s); atomicAdd(&sq[ch], q); }
    }
    __syncthreads();
    if (t < 13) { atomicAdd(&g_stats[t], ss[t]); atomicAdd(&g_stats[64 + t], sq[t]); }
}

// first-layer matmul (din=13): ht = dinv * (bn(x) @ W)
__global__ void k_matmul13(const float* __restrict__ in, const float* __restrict__ W,
                           const float* __restrict__ gma, const float* __restrict__ bta) {
    __shared__ float Wsh[13 * 32];
    __shared__ float ssh[13], shsh[13];
    int t = threadIdx.x;
    for (int i = t; i < 13 * 32; i += 256) Wsh[i] = W[i];
    if (t < 13) {
        float inv_n = 1.0f / (float)NN;
        float mu  = g_stats[t] * inv_n;
        float var = g_stats[64 + t] * inv_n - mu * mu;
        float sc  = gma[t] * rsqrtf(var + BN_EPS);
        ssh[t]  = sc;
        shsh[t] = bta[t] - mu * sc;
    }
    __syncthreads();
    int warp = t >> 5, j = t & 31;
    int node = blockIdx.x * 8 + warp;
    if (node >= NN) return;
    float a = (j < 13) ? (ssh[j] * in[node * 13 + j] + shsh[j]) : 0.f;
    float acc = 0.f;
#pragma unroll
    for (int k = 0; k < 13; k++) {
        float ak = __shfl_sync(0xffffffffu, a, k);
        acc += ak * Wsh[k * 32 + j];
    }
    g_ht[node * 32 + j] = acc * g_dinv[node];
}

// din=32 matmul: 4 nodes/warp, float4 lanes
__global__ void k_matmul32(const float* __restrict__ W, const float* __restrict__ st,
                           const float* __restrict__ gma, const float* __restrict__ bta) {
    __shared__ float4 Wsh4[32 * 8];
    __shared__ float ssh[32], shsh[32];
    int t = threadIdx.x;   // 256
    for (int i = t; i < 32 * 8; i += 256) Wsh4[i] = ((const float4*)W)[i];
    if (t < 32) {
        float inv_n = 1.0f / (float)NN;
        float mu  = st[t] * inv_n;
        float var = st[64 + t] * inv_n - mu * mu;
        float sc  = gma[t] * rsqrtf(var + BN_EPS);
        ssh[t]  = sc;
        shsh[t] = bta[t] - mu * sc;
    }
    __syncthreads();
    int warp = t >> 5, lane = t & 31;
    int l = lane & 7;
    int node = (blockIdx.x * 8 + warp) * 4 + (lane >> 3);
    float4 a4 = ((const float4*)g_y)[node * 8 + l];
    a4.x = ssh[l * 4 + 0] * a4.x + shsh[l * 4 + 0];
    a4.y = ssh[l * 4 + 1] * a4.y + shsh[l * 4 + 1];
    a4.z = ssh[l * 4 + 2] * a4.z + shsh[l * 4 + 2];
    a4.w = ssh[l * 4 + 3] * a4.w + shsh[l * 4 + 3];
    float4 acc = make_float4(0.f, 0.f, 0.f, 0.f);
    int grpbase = lane & 24;
#pragma unroll
    for (int k = 0; k < 32; k++) {
        float comp = ((k & 3) == 0) ? a4.x : ((k & 3) == 1) ? a4.y : ((k & 3) == 2) ? a4.z : a4.w;
        float ak = __shfl_sync(0xffffffffu, comp, grpbase + (k >> 2));
        float4 wv = Wsh4[k * 8 + l];
        acc.x += ak * wv.x; acc.y += ak * wv.y; acc.z += ak * wv.z; acc.w += ak * wv.w;
    }
    float dvn = g_dinv[node];
    acc.x *= dvn; acc.y *= dvn; acc.z *= dvn; acc.w *= dvn;
    ((float4*)g_ht)[node * 8 + l] = acc;
}

// SpMM: batched full chunks (MLP=8) + masked tail. Segment = [ptr[c], ptr[c+1]).
// do_pool != 0 (last layer): pool into per-graph buckets instead of storing y.
__global__ void k_spmm(const float* __restrict__ b, float* __restrict__ st,
                       const int* __restrict__ batch, int do_pool) {
    __shared__ float bsh[32], bsum[32], bsq[32];
    __shared__ float psh[NG * 32];
    __shared__ float pcs[NG];
    int t = threadIdx.x;
    if (t < 32) { bsh[t] = b[t]; bsum[t] = 0.f; bsq[t] = 0.f; }
    if (do_pool) {
        if (t < NG * 32) psh[t] = 0.f;
        if (t < NG)      pcs[t] = 0.f;
    }
    __syncthreads();
    int warp = t >> 5, lane = t & 31;
    int g = lane >> 3, l = lane & 7;
    int c = blockIdx.x * 32 + warp;       // NN = 3125*32
    const float4* ht4 = (const float4*)g_ht;
    int s0 = g_ptr[c], s1 = g_ptr[c + 1];
    float dv = g_dinv[c];
    float4 h0 = ht4[c * 8 + l];
    float4 acc = make_float4(0.f, 0.f, 0.f, 0.f);

    int nfull = (s1 - s0) & ~31;
    int full_end = s0 + nfull;
    for (int base = s0; base < full_end; base += 32) {
        int2 ew = g_edge[base + lane];
        int   ssrc[8];
        float wwt[8];
#pragma unroll
        for (int q = 0; q < 8; q++) {
            ssrc[q] = __shfl_sync(0xffffffffu, ew.x, q * 4 + g);
            wwt[q]  = __int_as_float(__shfl_sync(0xffffffffu, ew.y, q * 4 + g));
        }
        float4 hv[8];
#pragma unroll
        for (int q = 0; q < 8; q++) hv[q] = ht4[ssrc[q] * 8 + l];
#pragma unroll
        for (int q = 0; q < 8; q++) {
            acc.x += wwt[q] * hv[q].x; acc.y += wwt[q] * hv[q].y;
            acc.z += wwt[q] * hv[q].z; acc.w += wwt[q] * hv[q].w;
        }
    }
    if (full_end < s1) {
        int idx = full_end + lane;
        int2 ew = (idx < s1) ? g_edge[idx] : make_int2(0, 0);
        int m = s1 - full_end;
        int iters = (m + 3) >> 2;
        for (int q = 0; q < iters; q++) {
            int srcl = q * 4 + g;
            int   ss = __shfl_sync(0xffffffffu, ew.x, srcl);
            float ww = __int_as_float(__shfl_sync(0xffffffffu, ew.y, srcl));
            float4 hv = ht4[ss * 8 + l];
            acc.x += ww * hv.x; acc.y += ww * hv.y; acc.z += ww * hv.z; acc.w += ww * hv.w;
        }
    }
#pragma unroll
    for (int off = 8; off <= 16; off <<= 1) {
        acc.x += __shfl_xor_sync(0xffffffffu, acc.x, off);
        acc.y += __shfl_xor_sync(0xffffffffu, acc.y, off);
        acc.z += __shfl_xor_sync(0xffffffffu, acc.z, off);
        acc.w += __shfl_xor_sync(0xffffffffu, acc.w, off);
    }
    float4 r4;
    r4.x = fmaxf(dv * (acc.x + h0.x) + bsh[l * 4 + 0], 0.f);
    r4.y = fmaxf(dv * (acc.y + h0.y) + bsh[l * 4 + 1], 0.f);
    r4.z = fmaxf(dv * (acc.z + h0.z) + bsh[l * 4 + 2], 0.f);
    r4.w = fmaxf(dv * (acc.w + h0.w) + bsh[l * 4 + 3], 0.f);
    if (g == 0) {
        atomicAdd(&bsum[l * 4 + 0], r4.x); atomicAdd(&bsq[l * 4 + 0], r4.x * r4.x);
        atomicAdd(&bsum[l * 4 + 1], r4.y); atomicAdd(&bsq[l * 4 + 1], r4.y * r4.y);
        atomicAdd(&bsum[l * 4 + 2], r4.z); atomicAdd(&bsq[l * 4 + 2], r4.z * r4.z);
        atomicAdd(&bsum[l * 4 + 3], r4.w); atomicAdd(&bsq[l * 4 + 3], r4.w * r4.w);
        if (do_pool) {
            int bg = batch[c];
            atomicAdd(&psh[bg * 32 + l * 4 + 0], r4.x);
            atomicAdd(&psh[bg * 32 + l * 4 + 1], r4.y);
            atomicAdd(&psh[bg * 32 + l * 4 + 2], r4.z);
            atomicAdd(&psh[bg * 32 + l * 4 + 3], r4.w);
            if (l == 0) atomicAdd(&pcs[bg], 1.f);
        } else {
            ((float4*)g_y)[c * 8 + l] = r4;
        }
    }
    __syncthreads();
    if (t < 32) { atomicAdd(&st[t], bsum[t]); atomicAdd(&st[64 + t], bsq[t]); }
    if (do_pool) {
        if (t < NG * 32) atomicAdd(&g_pool[t], psh[t]);
        if (t < NG)      atomicAdd(&g_pcnt[t], pcs[t]);
    }
}

// final: BN4 fold (stats slot 4) applied to per-graph means
__global__ void k_final(float* __restrict__ out,
                        const float* __restrict__ gma, const float* __restrict__ bta) {
    int t = threadIdx.x;        // 256
    int j = t & 31, g = t >> 5;
    const float* st = g_stats + 4 * 128;
    float inv_n = 1.0f / (float)NN;
    float mu  = st[j] * inv_n;
    float var = st[64 + j] * inv_n - mu * mu;
    float sc  = gma[j] * rsqrtf(var + BN_EPS);
    float sh  = bta[j] - mu * sc;
    float c = g_pcnt[g];
    if (c < 1.f) c = 1.f;
    out[t] = sc * (g_pool[t] / c) + sh;
}

// ---------------- launch ----------------
extern "C" void kernel_launch(void* const* d_in, const int* in_sizes, int n_in,
                              void* d_out, int out_size) {
    const float* x     = (const float*)d_in[0];
    const int*   ei    = (const int*)d_in[1];     // int32 (jax x64 disabled)
    const float* w     = (const float*)d_in[2];
    const int*   batch = (const int*)d_in[3];
    const float* W[4] = {(const float*)d_in[4], (const float*)d_in[6],
                         (const float*)d_in[8], (const float*)d_in[10]};
    const float* B[4] = {(const float*)d_in[5], (const float*)d_in[7],
                         (const float*)d_in[9], (const float*)d_in[11]};
    const float* G[5]; const float* BE[5];
    for (int i = 0; i < 5; i++) {
        G[i]  = (const float*)d_in[12 + 2 * i];
        BE[i] = (const float*)d_in[13 + 2 * i];
    }
    float* out = (float*)d_out;

    float* stats_base = nullptr;
    cudaGetSymbolAddress((void**)&stats_base, g_stats);

    k_zero<<<(NN + 255) / 256, 256>>>();                 // #0
    k_degcnt<<<(EE / 4 + 255) / 256, 256>>>(ei);         // #1
    k_scanlb<<<CHUNKS, 1024>>>();                        // #2
    k_scatter<<<(EE / 4 + 255) / 256, 256>>>(ei, w);     // #3  <- profiled slot
    k_dinv2<<<(NN + 7) / 8, 256>>>();                    // #4
    k_xstats<<<(NN + 255) / 256, 256>>>(x);              // #5

    for (int l = 0; l < 4; l++) {
        if (l == 0) k_matmul13<<<(NN + 7) / 8, 256>>>(x, W[0], G[0], BE[0]);
        else        k_matmul32<<<NN / 32, 256>>>(W[l], stats_base + 128 * l, G[l], BE[l]);
        k_spmm<<<NN / 32, 1024>>>(B[l], stats_base + 128 * (l + 1), batch, (l == 3) ? 1 : 0);
    }

    k_final<<<1, 256>>>(out, G[4], BE[4]);
}